// round 14
// baseline (speedup 1.0000x reference)
#include <cuda_runtime.h>
#include <cuda_fp16.h>
#include <cstdint>

using f16 = __half;

constexpr int HIDDEN = 1024;
constexpr int INTER  = 1408;
constexpr int NEXP   = 8;
constexpr int TOKENS = 8192;
constexpr int MAX_MTILES = TOKENS / 128 + NEXP;   // 72
constexpr int NT1 = INTER / 64;                    // 22 GEMM1 n-tiles
constexpr int NT2 = HIDDEN / 128;                  // 8 GEMM2 n-tiles
constexpr int W1SEG = 2 * INTER / 128;             // 22 col-blocks of 128
constexpr int W1C_CTAS = NEXP * W1SEG;             // 176 w1 convert workers
constexpr int W2C_CTAS = 44;                       // w2 convert workers
constexpr int G1_CTAS = MAX_MTILES * NT1;          // 1584
constexpr int G2_CTAS = MAX_MTILES * NT2;          // 576
constexpr int MEGA_CTAS = W1C_CTAS + W2C_CTAS + G1_CTAS + G2_CTAS;  // 2380

// ---------------- scratch (device globals; no allocation allowed) ----------
__device__ __align__(256) f16 g_x[(size_t)TOKENS * HIDDEN];
__device__ __align__(256) f16 g_w1[(size_t)NEXP * HIDDEN * 2 * INTER];  // [E][K][N]
__device__ __align__(256) f16 g_w2[(size_t)NEXP * INTER * HIDDEN];      // [E][K][N]
__device__ __align__(256) f16 g_h[(size_t)TOKENS * INTER];
__device__ int g_cnt_m[MAX_MTILES];   // GEMM1 n-tiles completed per m-tile
__device__ int g_cnt_w2;              // w2 convert CTAs completed
__device__ int g_flag_w1[W1C_CTAS];   // per (e, 128-col block) w1 segment done

// ---------------- helpers ---------------------------------------------------
__device__ __forceinline__ bool map_tile(const void* tpe_ptr, int tile,
                                         int& eidx, int& off, int& cnt, int& m0) {
    int cnts[NEXP];
    const int* p32 = (const int*)tpe_ptr;
    int s = 0;
#pragma unroll
    for (int i = 0; i < NEXP; i++) s += p32[i];
    if (s == TOKENS) {
#pragma unroll
        for (int i = 0; i < NEXP; i++) cnts[i] = p32[i];
    } else {
        const long long* p64 = (const long long*)tpe_ptr;
#pragma unroll
        for (int i = 0; i < NEXP; i++) cnts[i] = (int)p64[i];
    }
    int acc_t = 0, acc_o = 0;
    bool found = false;
#pragma unroll
    for (int e = 0; e < NEXP; e++) {
        int t = (cnts[e] + 127) >> 7;
        if (!found && tile >= acc_t && tile < acc_t + t) {
            eidx = e; off = acc_o; cnt = cnts[e]; m0 = (tile - acc_t) * 128;
            found = true;
        }
        acc_t += t; acc_o += cnts[e];
    }
    return found;
}

__device__ __forceinline__ uint32_t smem_u32(const void* p) {
    uint32_t a;
    asm("{ .reg .u64 t; cvta.to.shared.u64 t, %1; cvt.u32.u64 %0, t; }"
        : "=r"(a) : "l"(p));
    return a;
}

#define SW128(o) ((o) ^ (((o) >> 3) & 0x70))

__device__ __forceinline__ void cp16(uint32_t s, const void* g, int nbytes) {
    asm volatile("cp.async.cg.shared.global [%0], [%1], 16, %2;"
                 :: "r"(s), "l"(g), "r"(nbytes) : "memory");
}

__device__ __forceinline__ void ldmx4(uint32_t* r, uint32_t addr) {
    asm volatile("ldmatrix.sync.aligned.m8n8.x4.shared.b16 {%0,%1,%2,%3}, [%4];"
                 : "=r"(r[0]), "=r"(r[1]), "=r"(r[2]), "=r"(r[3]) : "r"(addr));
}

__device__ __forceinline__ void ldmx4t(uint32_t* r, uint32_t addr) {
    asm volatile("ldmatrix.sync.aligned.m8n8.x4.trans.shared.b16 {%0,%1,%2,%3}, [%4];"
                 : "=r"(r[0]), "=r"(r[1]), "=r"(r[2]), "=r"(r[3]) : "r"(addr));
}

__device__ __forceinline__ void mma16816(float* c, const uint32_t* a, const uint32_t* b) {
    asm volatile("mma.sync.aligned.m16n8k16.row.col.f32.f16.f16.f32 "
                 "{%0,%1,%2,%3}, {%4,%5,%6,%7}, {%8,%9}, {%0,%1,%2,%3};"
                 : "+f"(c[0]), "+f"(c[1]), "+f"(c[2]), "+f"(c[3])
                 : "r"(a[0]), "r"(a[1]), "r"(a[2]), "r"(a[3]),
                   "r"(b[0]), "r"(b[1]));
}

__device__ __forceinline__ void cvt4(const float* __restrict__ src,
                                     f16* __restrict__ dst, size_t i) {
    float4 v = ((const float4*)src)[i];
    __half2 a = __floats2half2_rn(v.x, v.y);
    __half2 b = __floats2half2_rn(v.z, v.w);
    ((uint2*)dst)[i] = make_uint2(*(uint32_t*)&a, *(uint32_t*)&b);
}

// ---------------- prep kernel: zero counters + convert x --------------------
__global__ __launch_bounds__(256) void prep_kernel(
    const float* __restrict__ x, f16* __restrict__ xf, int nx4)
{
    if (blockIdx.x == 0) {
        for (int i = threadIdx.x; i < MAX_MTILES + 1 + W1C_CTAS; i += 256) {
            if (i < MAX_MTILES) g_cnt_m[i] = 0;
            else if (i == MAX_MTILES) g_cnt_w2 = 0;
            else g_flag_w1[i - MAX_MTILES - 1] = 0;
        }
    }
    int i = blockIdx.x * 256 + threadIdx.x;
    if (i < nx4) cvt4(x, xf, i);
}

// ---------------- GEMM body (shared by both GEMM phases) ---------------------
constexpr int BM = 128, BK = 64;
constexpr int A_SZ = BM * BK * 2;                // 16384
constexpr int B_SZ = BK * 128 * 2;               // 16384
constexpr int STAGE_SZ = A_SZ + B_SZ;            // 32768
constexpr int NSTAGE = 3;
constexpr int SMEM_BYTES = NSTAGE * STAGE_SZ;    // 98304 -> 2 CTAs/SM

template <int K, bool FUSED>
__device__ __forceinline__ void gemm_body(
    const f16* __restrict__ A, const f16* __restrict__ B,
    float* __restrict__ Cout, f16* __restrict__ H,
    int eidx, int off, int cnt, int m0, int ntile)
{
    const int n0 = ntile * (FUSED ? 64 : 128);
    constexpr int NFULL = FUSED ? 2 * INTER : HIDDEN;

    extern __shared__ char smem[];
    const uint32_t sbase = smem_u32(smem);
    const int tid = threadIdx.x, wid = tid >> 5, lane = tid & 31;

    const f16* Ag = A + (size_t)off * K;
    const f16* Bg = B + (size_t)eidx * ((size_t)K * NFULL);

    const int wm = (wid & 1) * 64;
    const int wn = (wid >> 1) * 32;
    const int g = lane >> 3, r8 = lane & 7;

    int a_base[4];
#pragma unroll
    for (int mi = 0; mi < 4; mi++)
        a_base[mi] = (wm + mi * 16 + r8 + (g & 1) * 8) * 128 + (g >> 1) * 16;

    const int b_k_byte = ((g & 1) * 8 + r8) * 256;
    const int b_chunk_half = (g >> 1);

    const int a_row0 = tid >> 3, a_ks = tid & 7;
    const int b_k0 = tid >> 4, b_c = tid & 15;

    float acc[4][4][4];
#pragma unroll
    for (int mi = 0; mi < 4; mi++)
#pragma unroll
        for (int ni = 0; ni < 4; ni++)
#pragma unroll
            for (int q = 0; q < 4; q++) acc[mi][ni][q] = 0.0f;

    constexpr int NCH = K / BK;

    auto load_stage = [&](int c) {
        const uint32_t st = sbase + (c % NSTAGE) * STAGE_SZ;
        const int k0 = c * BK;
#pragma unroll
        for (int i = 0; i < 4; ++i) {
            int row = a_row0 + i * 32;
            int gr = m0 + row;
            int nb = (gr < cnt) ? 16 : 0;
            int grc = (gr < cnt) ? gr : 0;
            cp16(st + SW128(row * 128 + a_ks * 16),
                 Ag + (size_t)grc * K + k0 + a_ks * 8, nb);
        }
#pragma unroll
        for (int i = 0; i < 4; ++i) {
            int k = b_k0 + i * 16;
            int wc = b_c ^ (k & 7);
            int gcol = FUSED ? ((b_c < 8) ? (n0 + b_c * 8)
                                          : (INTER + n0 + (b_c - 8) * 8))
                             : (n0 + b_c * 8);
            cp16(st + A_SZ + k * 256 + wc * 16,
                 Bg + (size_t)(k0 + k) * NFULL + gcol, 16);
        }
        asm volatile("cp.async.commit_group;" ::: "memory");
    };

    load_stage(0);
    if (NCH > 1) load_stage(1);

    for (int c = 0; c < NCH; ++c) {
        if (c + 1 < NCH)
            asm volatile("cp.async.wait_group 1;" ::: "memory");
        else
            asm volatile("cp.async.wait_group 0;" ::: "memory");
        __syncthreads();
        if (c + 2 < NCH) load_stage(c + 2);

        const uint32_t st = sbase + (c % NSTAGE) * STAGE_SZ;
        const uint32_t sA = st, sB = st + A_SZ;

#pragma unroll
        for (int kk = 0; kk < 4; ++kk) {
            uint32_t b[4][2];
#pragma unroll
            for (int j = 0; j < 2; ++j) {
                int chunk = (((wn >> 3) + j * 2 + b_chunk_half) ^ r8) & 15;
                uint32_t t[4];
                ldmx4t(t, sB + kk * 16 * 256 + b_k_byte + chunk * 16);
                b[j * 2][0] = t[0];     b[j * 2][1] = t[1];
                b[j * 2 + 1][0] = t[2]; b[j * 2 + 1][1] = t[3];
            }
#pragma unroll
            for (int mi = 0; mi < 4; mi++) {
                uint32_t a[4];
                ldmx4(a, sA + SW128(a_base[mi] + kk * 32));
#pragma unroll
                for (int ni = 0; ni < 4; ni++)
                    mma16816(acc[mi][ni], a, b[ni]);
            }
        }
    }
    __syncthreads();

    // epilogue: stage accum through SMEM
    float* shf = (float*)smem;
    const int crow = wm + (lane >> 2);
    const int ccol0 = wn + (lane & 3) * 2;
#pragma unroll
    for (int mi = 0; mi < 4; mi++)
#pragma unroll
        for (int ni = 0; ni < 4; ni++) {
            int rr = crow + mi * 16, cc = ccol0 + ni * 8;
            *(float2*)&shf[rr * 132 + cc]       = make_float2(acc[mi][ni][0], acc[mi][ni][1]);
            *(float2*)&shf[(rr + 8) * 132 + cc] = make_float2(acc[mi][ni][2], acc[mi][ni][3]);
        }
    __syncthreads();

    if (FUSED) {
        for (int idx = tid; idx < 128 * 32; idx += 256) {
            int rr = idx >> 5, j = (idx & 31) * 2;
            if (m0 + rr >= cnt) continue;
            float g0 = shf[rr * 132 + j],      g1 = shf[rr * 132 + j + 1];
            float u0 = shf[rr * 132 + 64 + j], u1 = shf[rr * 132 + 64 + j + 1];
            float h0 = u0 * g0 / (1.0f + __expf(-g0));
            float h1 = u1 * g1 / (1.0f + __expf(-g1));
            __half2 hp = __floats2half2_rn(h0, h1);
            *(uint32_t*)(H + (size_t)(off + m0 + rr) * INTER + n0 + j) =
                *(uint32_t*)&hp;
        }
    } else {
        for (int idx = tid; idx < 128 * 32; idx += 256) {
            int rr = idx >> 5, cu = idx & 31;
            if (m0 + rr >= cnt) continue;
            *(float4*)(Cout + (size_t)(off + m0 + rr) * HIDDEN + n0 + cu * 4) =
                *(float4*)&shf[rr * 132 + cu * 4];
        }
    }
}

// ---------------- mega kernel: w1-cvt | w2-cvt | GEMM1 | GEMM2 --------------
__global__ __launch_bounds__(256, 2) void moe_mega(
    const f16* __restrict__ xf, const f16* __restrict__ w1f,
    const f16* __restrict__ w2f, f16* __restrict__ hf,
    float* __restrict__ out, const void* __restrict__ tpe,
    const float* __restrict__ w1src, const float* __restrict__ w2src, int n24)
{
    const int tid = threadIdx.x;
    int bid = blockIdx.x;

    if (bid < W1C_CTAS) {
        // w1 segment convert: expert e, 128-col block cb of [K=1024][N=2816]
        const int e = bid / W1SEG, cb = bid % W1SEG;
        const float* src = w1src + (size_t)e * HIDDEN * 2 * INTER + cb * 128;
        f16* dst = (f16*)w1f + (size_t)e * HIDDEN * 2 * INTER + cb * 128;
        for (int i = tid; i < HIDDEN * 32; i += 256) {
            int row = i >> 5, c4 = i & 31;
            size_t o = (size_t)row * (2 * INTER) + c4 * 4;
            float4 v = *(const float4*)(src + o);
            __half2 a = __floats2half2_rn(v.x, v.y);
            __half2 b = __floats2half2_rn(v.z, v.w);
            *(uint2*)(dst + o) = make_uint2(*(uint32_t*)&a, *(uint32_t*)&b);
        }
        __threadfence();
        __syncthreads();
        if (tid == 0) atomicExch(&g_flag_w1[bid], 1);
        return;
    }
    bid -= W1C_CTAS;

    if (bid < W2C_CTAS) {
        // w2 f32->f16 convert workers
        const int stride = W2C_CTAS * 256;
        for (int i = bid * 256 + tid; i < n24; i += stride)
            cvt4(w2src, (f16*)w2f, i);
        __threadfence();
        __syncthreads();
        if (tid == 0) atomicAdd(&g_cnt_w2, 1);
        return;
    }
    bid -= W2C_CTAS;

    if (bid < G1_CTAS) {
        // GEMM1 (x @ w1 -> swiglu -> h): wait for this ntile's two w1 segments
        int mtile = bid / NT1, ntile = bid % NT1;
        int eidx, off, cnt, m0;
        if (!map_tile(tpe, mtile, eidx, off, cnt, m0)) return;
        const int sg = eidx * W1SEG + (ntile >> 1);            // gate block
        const int su = eidx * W1SEG + (INTER / 128) + (ntile >> 1);  // up block
        if (tid == 0) {
            while (*(volatile int*)&g_flag_w1[sg] == 0) __nanosleep(128);
            while (*(volatile int*)&g_flag_w1[su] == 0) __nanosleep(128);
        }
        __syncthreads();
        __threadfence();
        gemm_body<HIDDEN, true>(xf, w1f, nullptr, hf, eidx, off, cnt, m0, ntile);
        __threadfence();
        __syncthreads();
        if (tid == 0) atomicAdd(&g_cnt_m[mtile], 1);
        return;
    }
    bid -= G1_CTAS;

    // GEMM2 (h @ w2 -> out): wait for this m-tile's h and for w2f
    int mtile = bid / NT2, ntile = bid % NT2;
    int eidx, off, cnt, m0;
    if (!map_tile(tpe, mtile, eidx, off, cnt, m0)) return;
    if (tid == 0) {
        while (*(volatile int*)&g_cnt_w2 < W2C_CTAS) __nanosleep(256);
        while (*(volatile int*)&g_cnt_m[mtile] < NT1) __nanosleep(256);
    }
    __syncthreads();
    __threadfence();
    gemm_body<INTER, false>(hf, w2f, out, nullptr, eidx, off, cnt, m0, ntile);
}

// ---------------- launch -----------------------------------------------------
extern "C" void kernel_launch(void* const* d_in, const int* in_sizes, int n_in,
                              void* d_out, int out_size) {
    const float* x    = (const float*)d_in[0];
    const float* w1   = (const float*)d_in[1];
    const float* w2   = (const float*)d_in[2];
    const void*  tpe  = d_in[3];
    float* out = (float*)d_out;

    f16 *xf, *w1f, *w2f, *hf;
    cudaGetSymbolAddress((void**)&xf,  g_x);
    cudaGetSymbolAddress((void**)&w1f, g_w1);
    cudaGetSymbolAddress((void**)&w2f, g_w2);
    cudaGetSymbolAddress((void**)&hf,  g_h);

    int nx4 = TOKENS * HIDDEN / 4;
    int n24 = NEXP * INTER * HIDDEN / 4;

    // Launch 1: zero counters + convert x
    prep_kernel<<<(nx4 + 255) / 256, 256>>>(x, xf, nx4);

    // Launch 2: mega kernel (w1/w2 converts + GEMM1 + dependent GEMM2)
    cudaFuncSetAttribute(moe_mega,
                         cudaFuncAttributeMaxDynamicSharedMemorySize, SMEM_BYTES);
    moe_mega<<<MEGA_CTAS, 256, SMEM_BYTES>>>(xf, w1f, w2f, hf, out, tpe,
                                             w1, w2, n24);
}

// round 15
// speedup vs baseline: 1.0319x; 1.0319x over previous
#include <cuda_runtime.h>
#include <cuda_fp16.h>
#include <cstdint>

using f16 = __half;

constexpr int HIDDEN = 1024;
constexpr int INTER  = 1408;
constexpr int NEXP   = 8;
constexpr int TOKENS = 8192;
constexpr int MAX_MTILES = TOKENS / 128 + NEXP;   // 72
constexpr int NT1 = INTER / 64;                    // 22 GEMM1 n-tiles
constexpr int NT2 = HIDDEN / 128;                  // 8 GEMM2 n-tiles
constexpr int W1C_CTAS = 220;                      // w1 convert workers
constexpr int W2C_CTAS = 44;                       // w2 convert workers
constexpr int G1_CTAS = MAX_MTILES * NT1;          // 1584
constexpr int G2_CTAS = MAX_MTILES * NT2;          // 576
constexpr int MEGA_CTAS = W1C_CTAS + W2C_CTAS + G1_CTAS + G2_CTAS;  // 2424
constexpr int W1_EXP4 = HIDDEN * 2 * INTER / 4;    // f32x4 units per expert

// ---------------- scratch (device globals; no allocation allowed) ----------
__device__ __align__(256) f16 g_x[(size_t)TOKENS * HIDDEN];
__device__ __align__(256) f16 g_w1[(size_t)NEXP * HIDDEN * 2 * INTER];  // [E][K][N]
__device__ __align__(256) f16 g_w2[(size_t)NEXP * INTER * HIDDEN];      // [E][K][N]
__device__ __align__(256) f16 g_h[(size_t)TOKENS * INTER];
__device__ int g_cnt_m[MAX_MTILES];   // GEMM1 n-tiles completed per m-tile
__device__ int g_cnt_w2;              // w2 convert CTAs completed
__device__ int g_cnt_w1[NEXP];        // w1 convert CTAs completed per expert

// ---------------- helpers ---------------------------------------------------
__device__ __forceinline__ bool map_tile(const void* tpe_ptr, int tile,
                                         int& eidx, int& off, int& cnt, int& m0) {
    int cnts[NEXP];
    const int* p32 = (const int*)tpe_ptr;
    int s = 0;
#pragma unroll
    for (int i = 0; i < NEXP; i++) s += p32[i];
    if (s == TOKENS) {
#pragma unroll
        for (int i = 0; i < NEXP; i++) cnts[i] = p32[i];
    } else {
        const long long* p64 = (const long long*)tpe_ptr;
#pragma unroll
        for (int i = 0; i < NEXP; i++) cnts[i] = (int)p64[i];
    }
    int acc_t = 0, acc_o = 0;
    bool found = false;
#pragma unroll
    for (int e = 0; e < NEXP; e++) {
        int t = (cnts[e] + 127) >> 7;
        if (!found && tile >= acc_t && tile < acc_t + t) {
            eidx = e; off = acc_o; cnt = cnts[e]; m0 = (tile - acc_t) * 128;
            found = true;
        }
        acc_t += t; acc_o += cnts[e];
    }
    return found;
}

__device__ __forceinline__ uint32_t smem_u32(const void* p) {
    uint32_t a;
    asm("{ .reg .u64 t; cvta.to.shared.u64 t, %1; cvt.u32.u64 %0, t; }"
        : "=r"(a) : "l"(p));
    return a;
}

#define SW128(o) ((o) ^ (((o) >> 3) & 0x70))

__device__ __forceinline__ void cp16(uint32_t s, const void* g, int nbytes) {
    asm volatile("cp.async.cg.shared.global [%0], [%1], 16, %2;"
                 :: "r"(s), "l"(g), "r"(nbytes) : "memory");
}

__device__ __forceinline__ void ldmx4(uint32_t* r, uint32_t addr) {
    asm volatile("ldmatrix.sync.aligned.m8n8.x4.shared.b16 {%0,%1,%2,%3}, [%4];"
                 : "=r"(r[0]), "=r"(r[1]), "=r"(r[2]), "=r"(r[3]) : "r"(addr));
}

__device__ __forceinline__ void ldmx4t(uint32_t* r, uint32_t addr) {
    asm volatile("ldmatrix.sync.aligned.m8n8.x4.trans.shared.b16 {%0,%1,%2,%3}, [%4];"
                 : "=r"(r[0]), "=r"(r[1]), "=r"(r[2]), "=r"(r[3]) : "r"(addr));
}

__device__ __forceinline__ void mma16816(float* c, const uint32_t* a, const uint32_t* b) {
    asm volatile("mma.sync.aligned.m16n8k16.row.col.f32.f16.f16.f32 "
                 "{%0,%1,%2,%3}, {%4,%5,%6,%7}, {%8,%9}, {%0,%1,%2,%3};"
                 : "+f"(c[0]), "+f"(c[1]), "+f"(c[2]), "+f"(c[3])
                 : "r"(a[0]), "r"(a[1]), "r"(a[2]), "r"(a[3]),
                   "r"(b[0]), "r"(b[1]));
}

__device__ __forceinline__ void cvt4(const float* __restrict__ src,
                                     f16* __restrict__ dst, size_t i) {
    float4 v = ((const float4*)src)[i];
    __half2 a = __floats2half2_rn(v.x, v.y);
    __half2 b = __floats2half2_rn(v.z, v.w);
    ((uint2*)dst)[i] = make_uint2(*(uint32_t*)&a, *(uint32_t*)&b);
}

// ---------------- prep kernel: zero counters + convert x --------------------
__global__ __launch_bounds__(256) void prep_kernel(
    const float* __restrict__ x, f16* __restrict__ xf, int nx4)
{
    if (blockIdx.x == 0 && threadIdx.x < MAX_MTILES + 1 + NEXP) {
        int i = threadIdx.x;
        if (i < MAX_MTILES) g_cnt_m[i] = 0;
        else if (i == MAX_MTILES) g_cnt_w2 = 0;
        else g_cnt_w1[i - MAX_MTILES - 1] = 0;
    }
    int i = blockIdx.x * 256 + threadIdx.x;
    if (i < nx4) cvt4(x, xf, i);
}

// ---------------- GEMM body (shared by both GEMM phases) ---------------------
constexpr int BM = 128, BK = 64;
constexpr int A_SZ = BM * BK * 2;                // 16384
constexpr int B_SZ = BK * 128 * 2;               // 16384
constexpr int STAGE_SZ = A_SZ + B_SZ;            // 32768
constexpr int NSTAGE = 3;
constexpr int SMEM_BYTES = NSTAGE * STAGE_SZ;    // 98304 -> 2 CTAs/SM

template <int K, bool FUSED>
__device__ __forceinline__ void gemm_body(
    const f16* __restrict__ A, const f16* __restrict__ B,
    float* __restrict__ Cout, f16* __restrict__ H,
    int eidx, int off, int cnt, int m0, int ntile)
{
    const int n0 = ntile * (FUSED ? 64 : 128);
    constexpr int NFULL = FUSED ? 2 * INTER : HIDDEN;

    extern __shared__ char smem[];
    const uint32_t sbase = smem_u32(smem);
    const int tid = threadIdx.x, wid = tid >> 5, lane = tid & 31;

    const f16* Ag = A + (size_t)off * K;
    const f16* Bg = B + (size_t)eidx * ((size_t)K * NFULL);

    const int wm = (wid & 1) * 64;
    const int wn = (wid >> 1) * 32;
    const int g = lane >> 3, r8 = lane & 7;

    int a_base[4];
#pragma unroll
    for (int mi = 0; mi < 4; mi++)
        a_base[mi] = (wm + mi * 16 + r8 + (g & 1) * 8) * 128 + (g >> 1) * 16;

    const int b_k_byte = ((g & 1) * 8 + r8) * 256;
    const int b_chunk_half = (g >> 1);

    const int a_row0 = tid >> 3, a_ks = tid & 7;
    const int b_k0 = tid >> 4, b_c = tid & 15;

    float acc[4][4][4];
#pragma unroll
    for (int mi = 0; mi < 4; mi++)
#pragma unroll
        for (int ni = 0; ni < 4; ni++)
#pragma unroll
            for (int q = 0; q < 4; q++) acc[mi][ni][q] = 0.0f;

    constexpr int NCH = K / BK;

    auto load_stage = [&](int c) {
        const uint32_t st = sbase + (c % NSTAGE) * STAGE_SZ;
        const int k0 = c * BK;
#pragma unroll
        for (int i = 0; i < 4; ++i) {
            int row = a_row0 + i * 32;
            int gr = m0 + row;
            int nb = (gr < cnt) ? 16 : 0;
            int grc = (gr < cnt) ? gr : 0;
            cp16(st + SW128(row * 128 + a_ks * 16),
                 Ag + (size_t)grc * K + k0 + a_ks * 8, nb);
        }
#pragma unroll
        for (int i = 0; i < 4; ++i) {
            int k = b_k0 + i * 16;
            int wc = b_c ^ (k & 7);
            int gcol = FUSED ? ((b_c < 8) ? (n0 + b_c * 8)
                                          : (INTER + n0 + (b_c - 8) * 8))
                             : (n0 + b_c * 8);
            cp16(st + A_SZ + k * 256 + wc * 16,
                 Bg + (size_t)(k0 + k) * NFULL + gcol, 16);
        }
        asm volatile("cp.async.commit_group;" ::: "memory");
    };

    load_stage(0);
    if (NCH > 1) load_stage(1);

    for (int c = 0; c < NCH; ++c) {
        if (c + 1 < NCH)
            asm volatile("cp.async.wait_group 1;" ::: "memory");
        else
            asm volatile("cp.async.wait_group 0;" ::: "memory");
        __syncthreads();
        if (c + 2 < NCH) load_stage(c + 2);

        const uint32_t st = sbase + (c % NSTAGE) * STAGE_SZ;
        const uint32_t sA = st, sB = st + A_SZ;

#pragma unroll
        for (int kk = 0; kk < 4; ++kk) {
            uint32_t b[4][2];
#pragma unroll
            for (int j = 0; j < 2; ++j) {
                int chunk = (((wn >> 3) + j * 2 + b_chunk_half) ^ r8) & 15;
                uint32_t t[4];
                ldmx4t(t, sB + kk * 16 * 256 + b_k_byte + chunk * 16);
                b[j * 2][0] = t[0];     b[j * 2][1] = t[1];
                b[j * 2 + 1][0] = t[2]; b[j * 2 + 1][1] = t[3];
            }
#pragma unroll
            for (int mi = 0; mi < 4; mi++) {
                uint32_t a[4];
                ldmx4(a, sA + SW128(a_base[mi] + kk * 32));
#pragma unroll
                for (int ni = 0; ni < 4; ni++)
                    mma16816(acc[mi][ni], a, b[ni]);
            }
        }
    }
    __syncthreads();

    // epilogue: stage accum through SMEM
    float* shf = (float*)smem;
    const int crow = wm + (lane >> 2);
    const int ccol0 = wn + (lane & 3) * 2;
#pragma unroll
    for (int mi = 0; mi < 4; mi++)
#pragma unroll
        for (int ni = 0; ni < 4; ni++) {
            int rr = crow + mi * 16, cc = ccol0 + ni * 8;
            *(float2*)&shf[rr * 132 + cc]       = make_float2(acc[mi][ni][0], acc[mi][ni][1]);
            *(float2*)&shf[(rr + 8) * 132 + cc] = make_float2(acc[mi][ni][2], acc[mi][ni][3]);
        }
    __syncthreads();

    if (FUSED) {
        for (int idx = tid; idx < 128 * 32; idx += 256) {
            int rr = idx >> 5, j = (idx & 31) * 2;
            if (m0 + rr >= cnt) continue;
            float g0 = shf[rr * 132 + j],      g1 = shf[rr * 132 + j + 1];
            float u0 = shf[rr * 132 + 64 + j], u1 = shf[rr * 132 + 64 + j + 1];
            float h0 = u0 * g0 / (1.0f + __expf(-g0));
            float h1 = u1 * g1 / (1.0f + __expf(-g1));
            __half2 hp = __floats2half2_rn(h0, h1);
            *(uint32_t*)(H + (size_t)(off + m0 + rr) * INTER + n0 + j) =
                *(uint32_t*)&hp;
        }
    } else {
        for (int idx = tid; idx < 128 * 32; idx += 256) {
            int rr = idx >> 5, cu = idx & 31;
            if (m0 + rr >= cnt) continue;
            *(float4*)(Cout + (size_t)(off + m0 + rr) * HIDDEN + n0 + cu * 4) =
                *(float4*)&shf[rr * 132 + cu * 4];
        }
    }
}

// ---------------- mega kernel: w1-cvt | w2-cvt | GEMM1 | GEMM2 --------------
__global__ __launch_bounds__(256, 2) void moe_mega(
    const f16* __restrict__ xf, const f16* __restrict__ w1f,
    const f16* __restrict__ w2f, f16* __restrict__ hf,
    float* __restrict__ out, const void* __restrict__ tpe,
    const float* __restrict__ w1src, const float* __restrict__ w2src, int n24)
{
    const int tid = threadIdx.x;
    int bid = blockIdx.x;

    if (bid < W1C_CTAS) {
        // w1 convert, EXPERT-SEQUENTIAL: all 220 CTAs sweep expert 0 first,
        // flag it, then expert 1, ... GEMM1 expert-e tiles wake after ~(e+1)
        // sweep periods instead of waiting for the whole convert.
        const int stride = W1C_CTAS * 256;
#pragma unroll 1
        for (int e = 0; e < NEXP; ++e) {
            const float* src = w1src + (size_t)e * (4 * (size_t)W1_EXP4);
            f16* dst = (f16*)w1f + (size_t)e * (4 * (size_t)W1_EXP4);
            for (int i = bid * 256 + tid; i < W1_EXP4; i += stride)
                cvt4(src, dst, i);
            __threadfence();
            __syncthreads();
            if (tid == 0) atomicAdd(&g_cnt_w1[e], 1);
        }
        return;
    }
    bid -= W1C_CTAS;

    if (bid < W2C_CTAS) {
        // w2 f32->f16 convert workers
        const int stride = W2C_CTAS * 256;
        for (int i = bid * 256 + tid; i < n24; i += stride)
            cvt4(w2src, (f16*)w2f, i);
        __threadfence();
        __syncthreads();
        if (tid == 0) atomicAdd(&g_cnt_w2, 1);
        return;
    }
    bid -= W2C_CTAS;

    if (bid < G1_CTAS) {
        // GEMM1: wait for this expert's w1 to be converted
        int mtile = bid / NT1, ntile = bid % NT1;
        int eidx, off, cnt, m0;
        if (!map_tile(tpe, mtile, eidx, off, cnt, m0)) return;
        if (tid == 0) {
            while (*(volatile int*)&g_cnt_w1[eidx] < W1C_CTAS) __nanosleep(128);
        }
        __syncthreads();
        __threadfence();
        gemm_body<HIDDEN, true>(xf, w1f, nullptr, hf, eidx, off, cnt, m0, ntile);
        __threadfence();
        __syncthreads();
        if (tid == 0) atomicAdd(&g_cnt_m[mtile], 1);
        return;
    }
    bid -= G1_CTAS;

    // GEMM2: wait for this m-tile's h and for w2f
    int mtile = bid / NT2, ntile = bid % NT2;
    int eidx, off, cnt, m0;
    if (!map_tile(tpe, mtile, eidx, off, cnt, m0)) return;
    if (tid == 0) {
        while (*(volatile int*)&g_cnt_w2 < W2C_CTAS) __nanosleep(256);
        while (*(volatile int*)&g_cnt_m[mtile] < NT1) __nanosleep(256);
    }
    __syncthreads();
    __threadfence();
    gemm_body<INTER, false>(hf, w2f, out, nullptr, eidx, off, cnt, m0, ntile);
}

// ---------------- launch -----------------------------------------------------
extern "C" void kernel_launch(void* const* d_in, const int* in_sizes, int n_in,
                              void* d_out, int out_size) {
    const float* x    = (const float*)d_in[0];
    const float* w1   = (const float*)d_in[1];
    const float* w2   = (const float*)d_in[2];
    const void*  tpe  = d_in[3];
    float* out = (float*)d_out;

    f16 *xf, *w1f, *w2f, *hf;
    cudaGetSymbolAddress((void**)&xf,  g_x);
    cudaGetSymbolAddress((void**)&w1f, g_w1);
    cudaGetSymbolAddress((void**)&w2f, g_w2);
    cudaGetSymbolAddress((void**)&hf,  g_h);

    int nx4 = TOKENS * HIDDEN / 4;
    int n24 = NEXP * INTER * HIDDEN / 4;

    // Launch 1: zero counters + convert x
    prep_kernel<<<(nx4 + 255) / 256, 256>>>(x, xf, nx4);

    // Launch 2: mega kernel (expert-sequential w1 convert + w2 convert
    //           + GEMM1 + dependent GEMM2)
    cudaFuncSetAttribute(moe_mega,
                         cudaFuncAttributeMaxDynamicSharedMemorySize, SMEM_BYTES);
    moe_mega<<<MEGA_CTAS, 256, SMEM_BYTES>>>(xf, w1f, w2f, hf, out, tpe,
                                             w1, w2, n24);
}

// round 16
// speedup vs baseline: 1.0802x; 1.0468x over previous
#include <cuda_runtime.h>
#include <cuda_fp16.h>
#include <cstdint>

using f16 = __half;

constexpr int HIDDEN = 1024;
constexpr int INTER  = 1408;
constexpr int NEXP   = 8;
constexpr int TOKENS = 8192;
constexpr int MAX_MTILES = TOKENS / 128 + NEXP;   // 72
constexpr int NT1 = INTER / 64;                    // 22 GEMM1 n-tiles
constexpr int NT2 = HIDDEN / 128;                  // 8 GEMM2 n-tiles
constexpr int CVT_CTAS = 44;                       // w2 convert workers
constexpr int G1_CTAS = MAX_MTILES * NT1;          // 1584
constexpr int G2_CTAS = MAX_MTILES * NT2;          // 576
constexpr int MEGA_CTAS = CVT_CTAS + G1_CTAS + G2_CTAS;
constexpr int PREP_CTAS = 2048;

// ---------------- scratch (device globals; no allocation allowed) ----------
__device__ __align__(256) f16 g_x[(size_t)TOKENS * HIDDEN];
__device__ __align__(256) f16 g_w1[(size_t)NEXP * HIDDEN * 2 * INTER];  // [E][K][N]
__device__ __align__(256) f16 g_w2[(size_t)NEXP * INTER * HIDDEN];      // [E][K][N]
__device__ __align__(256) f16 g_h[(size_t)TOKENS * INTER];
__device__ int g_cnt_m[MAX_MTILES];   // GEMM1 n-tiles completed per m-tile
__device__ int g_cnt_cvt;             // w2 convert CTAs completed

// ---------------- helpers ---------------------------------------------------
__device__ __forceinline__ bool map_tile(const void* tpe_ptr, int tile,
                                         int& eidx, int& off, int& cnt, int& m0) {
    int cnts[NEXP];
    const int* p32 = (const int*)tpe_ptr;
    int s = 0;
#pragma unroll
    for (int i = 0; i < NEXP; i++) s += p32[i];
    if (s == TOKENS) {
#pragma unroll
        for (int i = 0; i < NEXP; i++) cnts[i] = p32[i];
    } else {
        const long long* p64 = (const long long*)tpe_ptr;
#pragma unroll
        for (int i = 0; i < NEXP; i++) cnts[i] = (int)p64[i];
    }
    int acc_t = 0, acc_o = 0;
    bool found = false;
#pragma unroll
    for (int e = 0; e < NEXP; e++) {
        int t = (cnts[e] + 127) >> 7;
        if (!found && tile >= acc_t && tile < acc_t + t) {
            eidx = e; off = acc_o; cnt = cnts[e]; m0 = (tile - acc_t) * 128;
            found = true;
        }
        acc_t += t; acc_o += cnts[e];
    }
    return found;
}

__device__ __forceinline__ uint32_t smem_u32(const void* p) {
    uint32_t a;
    asm("{ .reg .u64 t; cvta.to.shared.u64 t, %1; cvt.u32.u64 %0, t; }"
        : "=r"(a) : "l"(p));
    return a;
}

#define SW128(o) ((o) ^ (((o) >> 3) & 0x70))

__device__ __forceinline__ void cp16(uint32_t s, const void* g, int nbytes) {
    asm volatile("cp.async.cg.shared.global [%0], [%1], 16, %2;"
                 :: "r"(s), "l"(g), "r"(nbytes) : "memory");
}

__device__ __forceinline__ void ldmx4(uint32_t* r, uint32_t addr) {
    asm volatile("ldmatrix.sync.aligned.m8n8.x4.shared.b16 {%0,%1,%2,%3}, [%4];"
                 : "=r"(r[0]), "=r"(r[1]), "=r"(r[2]), "=r"(r[3]) : "r"(addr));
}

__device__ __forceinline__ void ldmx4t(uint32_t* r, uint32_t addr) {
    asm volatile("ldmatrix.sync.aligned.m8n8.x4.trans.shared.b16 {%0,%1,%2,%3}, [%4];"
                 : "=r"(r[0]), "=r"(r[1]), "=r"(r[2]), "=r"(r[3]) : "r"(addr));
}

__device__ __forceinline__ void mma16816(float* c, const uint32_t* a, const uint32_t* b) {
    asm volatile("mma.sync.aligned.m16n8k16.row.col.f32.f16.f16.f32 "
                 "{%0,%1,%2,%3}, {%4,%5,%6,%7}, {%8,%9}, {%0,%1,%2,%3};"
                 : "+f"(c[0]), "+f"(c[1]), "+f"(c[2]), "+f"(c[3])
                 : "r"(a[0]), "r"(a[1]), "r"(a[2]), "r"(a[3]),
                   "r"(b[0]), "r"(b[1]));
}

__device__ __forceinline__ void cvt4(const float* __restrict__ src,
                                     f16* __restrict__ dst, size_t i) {
    float4 v = ((const float4*)src)[i];
    __half2 a = __floats2half2_rn(v.x, v.y);
    __half2 b = __floats2half2_rn(v.z, v.w);
    ((uint2*)dst)[i] = make_uint2(*(uint32_t*)&a, *(uint32_t*)&b);
}

// ---------------- prep kernel: counters + x & w1 converts (grid-stride) -----
// 2048 fat CTAs; each thread handles ~15 16B units, unrolled x4 for MLP.
__global__ __launch_bounds__(256) void prep_kernel(
    const float* __restrict__ x, f16* __restrict__ xf,
    const float* __restrict__ w1, f16* __restrict__ w1f,
    int nx4, int n14)
{
    if (blockIdx.x == 0 && threadIdx.x < MAX_MTILES + 1) {
        if (threadIdx.x < MAX_MTILES) g_cnt_m[threadIdx.x] = 0;
        else g_cnt_cvt = 0;
    }
    const int stride = PREP_CTAS * 256;
    const int base = blockIdx.x * 256 + threadIdx.x;
    const int total = nx4 + n14;

    int i = base;
    // unrolled main loop: 4 independent iterations in flight
    for (; i + 3 * stride < total; i += 4 * stride) {
#pragma unroll
        for (int u = 0; u < 4; ++u) {
            int j = i + u * stride;
            if (j < nx4) cvt4(x, xf, j);
            else         cvt4(w1, w1f, j - nx4);
        }
    }
    for (; i < total; i += stride) {
        if (i < nx4) cvt4(x, xf, i);
        else         cvt4(w1, w1f, i - nx4);
    }
}

// ---------------- GEMM body (shared by both GEMM phases) ---------------------
constexpr int BM = 128, BK = 64;
constexpr int A_SZ = BM * BK * 2;                // 16384
constexpr int B_SZ = BK * 128 * 2;               // 16384
constexpr int STAGE_SZ = A_SZ + B_SZ;            // 32768
constexpr int NSTAGE = 3;
constexpr int SMEM_BYTES = NSTAGE * STAGE_SZ;    // 98304 -> 2 CTAs/SM

template <int K, bool FUSED>
__device__ __forceinline__ void gemm_body(
    const f16* __restrict__ A, const f16* __restrict__ B,
    float* __restrict__ Cout, f16* __restrict__ H,
    int eidx, int off, int cnt, int m0, int ntile)
{
    const int n0 = ntile * (FUSED ? 64 : 128);
    constexpr int NFULL = FUSED ? 2 * INTER : HIDDEN;

    extern __shared__ char smem[];
    const uint32_t sbase = smem_u32(smem);
    const int tid = threadIdx.x, wid = tid >> 5, lane = tid & 31;

    const f16* Ag = A + (size_t)off * K;
    const f16* Bg = B + (size_t)eidx * ((size_t)K * NFULL);

    const int wm = (wid & 1) * 64;
    const int wn = (wid >> 1) * 32;
    const int g = lane >> 3, r8 = lane & 7;

    int a_base[4];
#pragma unroll
    for (int mi = 0; mi < 4; mi++)
        a_base[mi] = (wm + mi * 16 + r8 + (g & 1) * 8) * 128 + (g >> 1) * 16;

    const int b_k_byte = ((g & 1) * 8 + r8) * 256;
    const int b_chunk_half = (g >> 1);

    const int a_row0 = tid >> 3, a_ks = tid & 7;
    const int b_k0 = tid >> 4, b_c = tid & 15;

    float acc[4][4][4];
#pragma unroll
    for (int mi = 0; mi < 4; mi++)
#pragma unroll
        for (int ni = 0; ni < 4; ni++)
#pragma unroll
            for (int q = 0; q < 4; q++) acc[mi][ni][q] = 0.0f;

    constexpr int NCH = K / BK;

    auto load_stage = [&](int c) {
        const uint32_t st = sbase + (c % NSTAGE) * STAGE_SZ;
        const int k0 = c * BK;
#pragma unroll
        for (int i = 0; i < 4; ++i) {
            int row = a_row0 + i * 32;
            int gr = m0 + row;
            int nb = (gr < cnt) ? 16 : 0;
            int grc = (gr < cnt) ? gr : 0;
            cp16(st + SW128(row * 128 + a_ks * 16),
                 Ag + (size_t)grc * K + k0 + a_ks * 8, nb);
        }
#pragma unroll
        for (int i = 0; i < 4; ++i) {
            int k = b_k0 + i * 16;
            int wc = b_c ^ (k & 7);
            int gcol = FUSED ? ((b_c < 8) ? (n0 + b_c * 8)
                                          : (INTER + n0 + (b_c - 8) * 8))
                             : (n0 + b_c * 8);
            cp16(st + A_SZ + k * 256 + wc * 16,
                 Bg + (size_t)(k0 + k) * NFULL + gcol, 16);
        }
        asm volatile("cp.async.commit_group;" ::: "memory");
    };

    load_stage(0);
    if (NCH > 1) load_stage(1);

    for (int c = 0; c < NCH; ++c) {
        if (c + 1 < NCH)
            asm volatile("cp.async.wait_group 1;" ::: "memory");
        else
            asm volatile("cp.async.wait_group 0;" ::: "memory");
        __syncthreads();
        if (c + 2 < NCH) load_stage(c + 2);

        const uint32_t st = sbase + (c % NSTAGE) * STAGE_SZ;
        const uint32_t sA = st, sB = st + A_SZ;

#pragma unroll
        for (int kk = 0; kk < 4; ++kk) {
            uint32_t b[4][2];
#pragma unroll
            for (int j = 0; j < 2; ++j) {
                int chunk = (((wn >> 3) + j * 2 + b_chunk_half) ^ r8) & 15;
                uint32_t t[4];
                ldmx4t(t, sB + kk * 16 * 256 + b_k_byte + chunk * 16);
                b[j * 2][0] = t[0];     b[j * 2][1] = t[1];
                b[j * 2 + 1][0] = t[2]; b[j * 2 + 1][1] = t[3];
            }
#pragma unroll
            for (int mi = 0; mi < 4; mi++) {
                uint32_t a[4];
                ldmx4(a, sA + SW128(a_base[mi] + kk * 32));
#pragma unroll
                for (int ni = 0; ni < 4; ni++)
                    mma16816(acc[mi][ni], a, b[ni]);
            }
        }
    }
    __syncthreads();

    // epilogue: stage accum through SMEM
    float* shf = (float*)smem;
    const int crow = wm + (lane >> 2);
    const int ccol0 = wn + (lane & 3) * 2;
#pragma unroll
    for (int mi = 0; mi < 4; mi++)
#pragma unroll
        for (int ni = 0; ni < 4; ni++) {
            int rr = crow + mi * 16, cc = ccol0 + ni * 8;
            *(float2*)&shf[rr * 132 + cc]       = make_float2(acc[mi][ni][0], acc[mi][ni][1]);
            *(float2*)&shf[(rr + 8) * 132 + cc] = make_float2(acc[mi][ni][2], acc[mi][ni][3]);
        }
    __syncthreads();

    if (FUSED) {
        for (int idx = tid; idx < 128 * 32; idx += 256) {
            int rr = idx >> 5, j = (idx & 31) * 2;
            if (m0 + rr >= cnt) continue;
            float g0 = shf[rr * 132 + j],      g1 = shf[rr * 132 + j + 1];
            float u0 = shf[rr * 132 + 64 + j], u1 = shf[rr * 132 + 64 + j + 1];
            float h0 = u0 * g0 / (1.0f + __expf(-g0));
            float h1 = u1 * g1 / (1.0f + __expf(-g1));
            __half2 hp = __floats2half2_rn(h0, h1);
            *(uint32_t*)(H + (size_t)(off + m0 + rr) * INTER + n0 + j) =
                *(uint32_t*)&hp;
        }
    } else {
        for (int idx = tid; idx < 128 * 32; idx += 256) {
            int rr = idx >> 5, cu = idx & 31;
            if (m0 + rr >= cnt) continue;
            *(float4*)(Cout + (size_t)(off + m0 + rr) * HIDDEN + n0 + cu * 4) =
                *(float4*)&shf[rr * 132 + cu * 4];
        }
    }
}

// ---------------- mega kernel: w2-cvt | GEMM1 | GEMM2 (dep-counted) ---------
__global__ __launch_bounds__(256, 2) void moe_mega(
    const f16* __restrict__ xf, const f16* __restrict__ w1f,
    const f16* __restrict__ w2f, f16* __restrict__ hf,
    float* __restrict__ out, const void* __restrict__ tpe,
    const float* __restrict__ w2src, int n24)
{
    const int tid = threadIdx.x;
    int bid = blockIdx.x;

    if (bid < CVT_CTAS) {
        // w2 f32->f16 convert workers (wave 1, hidden under GEMM1)
        const int stride = CVT_CTAS * 256;
        for (int i = bid * 256 + tid; i < n24; i += stride)
            cvt4(w2src, (f16*)w2f, i);
        __threadfence();
        __syncthreads();
        if (tid == 0) atomicAdd(&g_cnt_cvt, 1);
        return;
    }
    bid -= CVT_CTAS;

    if (bid < G1_CTAS) {
        // GEMM1 (x @ w1 -> swiglu -> h), m-major ordering
        int mtile = bid / NT1, ntile = bid % NT1;
        int eidx, off, cnt, m0;
        if (!map_tile(tpe, mtile, eidx, off, cnt, m0)) return;
        gemm_body<HIDDEN, true>(xf, w1f, nullptr, hf, eidx, off, cnt, m0, ntile);
        __threadfence();            // publish this thread's h stores (gpu scope)
        __syncthreads();            // all threads of CTA have fenced
        if (tid == 0) atomicAdd(&g_cnt_m[mtile], 1);
        return;
    }
    bid -= G1_CTAS;

    // GEMM2 (h @ w2 -> out): wait for this m-tile's h and for w2f
    int mtile = bid / NT2, ntile = bid % NT2;
    int eidx, off, cnt, m0;
    if (!map_tile(tpe, mtile, eidx, off, cnt, m0)) return;
    if (tid == 0) {
        while (*(volatile int*)&g_cnt_cvt < CVT_CTAS) __nanosleep(256);
        while (*(volatile int*)&g_cnt_m[mtile] < NT1) __nanosleep(256);
    }
    __syncthreads();
    __threadfence();                // acquire: order subsequent reads
    gemm_body<INTER, false>(hf, w2f, out, nullptr, eidx, off, cnt, m0, ntile);
}

// ---------------- launch -----------------------------------------------------
extern "C" void kernel_launch(void* const* d_in, const int* in_sizes, int n_in,
                              void* d_out, int out_size) {
    const float* x    = (const float*)d_in[0];
    const float* w1   = (const float*)d_in[1];
    const float* w2   = (const float*)d_in[2];
    const void*  tpe  = d_in[3];
    float* out = (float*)d_out;

    f16 *xf, *w1f, *w2f, *hf;
    cudaGetSymbolAddress((void**)&xf,  g_x);
    cudaGetSymbolAddress((void**)&w1f, g_w1);
    cudaGetSymbolAddress((void**)&w2f, g_w2);
    cudaGetSymbolAddress((void**)&hf,  g_h);

    int nx4 = TOKENS * HIDDEN / 4;
    int n14 = NEXP * HIDDEN * 2 * INTER / 4;
    int n24 = NEXP * INTER * HIDDEN / 4;

    // Launch 1: zero counters + convert x and w1 (fat grid-stride CTAs)
    prep_kernel<<<PREP_CTAS, 256>>>(x, xf, w1, w1f, nx4, n14);

    // Launch 2: mega kernel (w2 convert + GEMM1 + dependent GEMM2)
    cudaFuncSetAttribute(moe_mega,
                         cudaFuncAttributeMaxDynamicSharedMemorySize, SMEM_BYTES);
    moe_mega<<<MEGA_CTAS, 256, SMEM_BYTES>>>(xf, w1f, w2f, hf, out, tpe, w2, n24);
}